// round 2
// baseline (speedup 1.0000x reference)
#include <cuda_runtime.h>
#include <cuda_bf16.h>
#include <stdint.h>

// Per-tier abs-max accumulators (slots 1..3 used; tier 0 is 16-bit passthrough).
// Non-negative float bit patterns order identically to unsigned ints, so
// atomicMax on the uint view computes float max exactly.
__device__ unsigned int g_absmax[4];

__global__ void init_absmax_kernel() {
    if (threadIdx.x < 4) g_absmax[threadIdx.x] = 0u;
}

// Fused abs-max over (tw_i * ts_i) for tiers 1..3, grid-stride over the
// concatenated float4 index space.
__global__ void absmax3_kernel(const float4* __restrict__ w1,
                               const float4* __restrict__ w2,
                               const float4* __restrict__ w3,
                               const float4* __restrict__ s1,
                               const float4* __restrict__ s2,
                               const float4* __restrict__ s3,
                               long n41, long n42, long n43, int dim4) {
    float m1 = 0.f, m2 = 0.f, m3 = 0.f;
    const long total = n41 + n42 + n43;
    const long b1 = n41, b2 = n41 + n42;
    long g = (long)blockIdx.x * blockDim.x + threadIdx.x;
    const long stride = (long)gridDim.x * blockDim.x;
    for (; g < total; g += stride) {
        const float4* w; const float4* s; long i; int sel;
        if (g < b1)      { w = w1; s = s1; i = g;      sel = 0; }
        else if (g < b2) { w = w2; s = s2; i = g - b1; sel = 1; }
        else             { w = w3; s = s3; i = g - b2; sel = 2; }
        float4 v = w[i];
        float4 sc = s[(int)(i % dim4)];
        float mm = fmaxf(fmaxf(fabsf(v.x * sc.x), fabsf(v.y * sc.y)),
                         fmaxf(fabsf(v.z * sc.z), fabsf(v.w * sc.w)));
        if (sel == 0)      m1 = fmaxf(m1, mm);
        else if (sel == 1) m2 = fmaxf(m2, mm);
        else               m3 = fmaxf(m3, mm);
    }

    // warp reduce all three
    #pragma unroll
    for (int o = 16; o; o >>= 1) {
        m1 = fmaxf(m1, __shfl_xor_sync(0xFFFFFFFFu, m1, o));
        m2 = fmaxf(m2, __shfl_xor_sync(0xFFFFFFFFu, m2, o));
        m3 = fmaxf(m3, __shfl_xor_sync(0xFFFFFFFFu, m3, o));
    }
    __shared__ float sm1[32], sm2[32], sm3[32];
    int lane = threadIdx.x & 31, wid = threadIdx.x >> 5;
    if (lane == 0) { sm1[wid] = m1; sm2[wid] = m2; sm3[wid] = m3; }
    __syncthreads();
    int nwarps = blockDim.x >> 5;
    if (wid == 0) {
        m1 = (lane < nwarps) ? sm1[lane] : 0.f;
        m2 = (lane < nwarps) ? sm2[lane] : 0.f;
        m3 = (lane < nwarps) ? sm3[lane] : 0.f;
        #pragma unroll
        for (int o = 16; o; o >>= 1) {
            m1 = fmaxf(m1, __shfl_xor_sync(0xFFFFFFFFu, m1, o));
            m2 = fmaxf(m2, __shfl_xor_sync(0xFFFFFFFFu, m2, o));
            m3 = fmaxf(m3, __shfl_xor_sync(0xFFFFFFFFu, m3, o));
        }
        if (lane == 0) {
            atomicMax(&g_absmax[1], __float_as_uint(m1));
            atomicMax(&g_absmax[2], __float_as_uint(m2));
            atomicMax(&g_absmax[3], __float_as_uint(m3));
        }
    }
}

// One block per output token. Compute the fake-quantized row on the fly.
// ids are int32 (JAX without x64 downcasts int64 -> int32).
__global__ void gather_kernel(const int* __restrict__ ids,
                              const float4* __restrict__ tw0,
                              const float4* __restrict__ tw1,
                              const float4* __restrict__ tw2,
                              const float4* __restrict__ tw3,
                              const float4* __restrict__ ts0,
                              const float4* __restrict__ ts1,
                              const float4* __restrict__ ts2,
                              const float4* __restrict__ ts3,
                              float4* __restrict__ out,
                              int dim4, long b0, long b1, long b2, long vocab) {
    const int tok = blockIdx.x;
    long id = (long)ids[tok];
    // Defensive clamp: a bad id becomes a wrong value (caught by rel_err),
    // not an illegal access.
    if (id < 0) id = 0;
    if (id >= vocab) id = vocab - 1;

    const float4* w; const float4* s;
    float mv = 0.f; int slot = 0;
    if (id < b0)      { w = tw0 + (size_t)id * dim4;        s = ts0; }
    else if (id < b1) { w = tw1 + (size_t)(id - b0) * dim4; s = ts1; mv = 127.f; slot = 1; }
    else if (id < b2) { w = tw2 + (size_t)(id - b1) * dim4; s = ts2; mv = 31.f;  slot = 2; }
    else              { w = tw3 + (size_t)(id - b2) * dim4; s = ts3; mv = 7.f;   slot = 3; }

    float scale = 1.f;
    if (slot > 0) scale = fmaxf(__uint_as_float(g_absmax[slot]), 1e-8f) / mv;

    float4* o = out + (size_t)tok * dim4;
    for (int c = threadIdx.x; c < dim4; c += blockDim.x) {
        float4 v = w[c];
        float4 sc = s[c];
        v.x *= sc.x; v.y *= sc.y; v.z *= sc.z; v.w *= sc.w;
        if (slot > 0) {
            v.x = fminf(fmaxf(rintf(v.x / scale), -mv), mv) * scale;
            v.y = fminf(fmaxf(rintf(v.y / scale), -mv), mv) * scale;
            v.z = fminf(fmaxf(rintf(v.z / scale), -mv), mv) * scale;
            v.w = fminf(fmaxf(rintf(v.w / scale), -mv), mv) * scale;
        }
        o[c] = v;
    }
}

extern "C" void kernel_launch(void* const* d_in, const int* in_sizes, int n_in,
                              void* d_out, int out_size) {
    const int*   ids = (const int*)d_in[0];
    const float* tw0 = (const float*)d_in[1];
    const float* tw1 = (const float*)d_in[2];
    const float* tw2 = (const float*)d_in[3];
    const float* tw3 = (const float*)d_in[4];
    const float* ts0 = (const float*)d_in[5];
    const float* ts1 = (const float*)d_in[6];
    const float* ts2 = (const float*)d_in[7];
    const float* ts3 = (const float*)d_in[8];

    const int dim  = in_sizes[5];          // ts0 element count = embedding dim
    const int dim4 = dim / 4;
    const int ntok = in_sizes[0];

    const long r0 = in_sizes[1] / dim;     // tier row counts
    const long r1 = in_sizes[2] / dim;
    const long r2 = in_sizes[3] / dim;
    const long r3 = in_sizes[4] / dim;
    const long b0 = r0;                    // cumulative id boundaries
    const long b1 = b0 + r1;
    const long b2 = b1 + r2;
    const long vocab = b2 + r3;

    const long n41 = (long)in_sizes[2] / 4;
    const long n42 = (long)in_sizes[3] / 4;
    const long n43 = (long)in_sizes[4] / 4;

    init_absmax_kernel<<<1, 32>>>();
    absmax3_kernel<<<2048, 256>>>(
        (const float4*)tw1, (const float4*)tw2, (const float4*)tw3,
        (const float4*)ts1, (const float4*)ts2, (const float4*)ts3,
        n41, n42, n43, dim4);
    gather_kernel<<<ntok, 128>>>(
        ids,
        (const float4*)tw0, (const float4*)tw1, (const float4*)tw2, (const float4*)tw3,
        (const float4*)ts0, (const float4*)ts1, (const float4*)ts2, (const float4*)ts3,
        (float4*)d_out, dim4, b0, b1, b2, vocab);
}

// round 3
// speedup vs baseline: 1.1969x; 1.1969x over previous
#include <cuda_runtime.h>
#include <cuda_bf16.h>
#include <stdint.h>

// Per-tier abs-max accumulators (slots 1..3 used; tier 0 is 16-bit passthrough).
// Non-negative float bit patterns order identically to unsigned ints, so
// atomicMax on the uint view computes float max exactly.
__device__ unsigned int g_absmax[4];

// Column-mapped abs-max: thread t owns float4 column (t % dim4); the scale
// value lives in a register; rows are strided across the blocks assigned to
// the tier. Manual 4x row unroll front-batches 4 independent LDG.128s.
__global__ void absmax3_kernel(const float4* __restrict__ w1,
                               const float4* __restrict__ w2,
                               const float4* __restrict__ w3,
                               const float4* __restrict__ s1,
                               const float4* __restrict__ s2,
                               const float4* __restrict__ s3,
                               int rows1, int rows2, int rows3,
                               int nb1, int nb2, int nb3, int dim4) {
    const int b = blockIdx.x;
    const float4* __restrict__ w;
    const float4* __restrict__ s;
    int rows, nb, bi, slot;
    if (b < nb1)            { w = w1; s = s1; rows = rows1; nb = nb1; bi = b;            slot = 1; }
    else if (b < nb1 + nb2) { w = w2; s = s2; rows = rows2; nb = nb2; bi = b - nb1;      slot = 2; }
    else                    { w = w3; s = s3; rows = rows3; nb = nb3; bi = b - nb1 - nb2;slot = 3; }

    const int c = threadIdx.x;           // blockDim.x == dim4 (256)
    const float4 sc = s[c];

    float m = 0.f;
    int r = bi;
    const int stride = nb;
    for (; r + 3 * stride < rows; r += 4 * stride) {
        float4 a0 = w[(size_t)r * dim4 + c];
        float4 a1 = w[(size_t)(r + stride) * dim4 + c];
        float4 a2 = w[(size_t)(r + 2 * stride) * dim4 + c];
        float4 a3 = w[(size_t)(r + 3 * stride) * dim4 + c];
        float m0 = fmaxf(fmaxf(fabsf(a0.x * sc.x), fabsf(a0.y * sc.y)),
                         fmaxf(fabsf(a0.z * sc.z), fabsf(a0.w * sc.w)));
        float m1 = fmaxf(fmaxf(fabsf(a1.x * sc.x), fabsf(a1.y * sc.y)),
                         fmaxf(fabsf(a1.z * sc.z), fabsf(a1.w * sc.w)));
        float m2 = fmaxf(fmaxf(fabsf(a2.x * sc.x), fabsf(a2.y * sc.y)),
                         fmaxf(fabsf(a2.z * sc.z), fabsf(a2.w * sc.w)));
        float m3 = fmaxf(fmaxf(fabsf(a3.x * sc.x), fabsf(a3.y * sc.y)),
                         fmaxf(fabsf(a3.z * sc.z), fabsf(a3.w * sc.w)));
        m = fmaxf(m, fmaxf(fmaxf(m0, m1), fmaxf(m2, m3)));
    }
    for (; r < rows; r += stride) {
        float4 a = w[(size_t)r * dim4 + c];
        m = fmaxf(m, fmaxf(fmaxf(fabsf(a.x * sc.x), fabsf(a.y * sc.y)),
                           fmaxf(fabsf(a.z * sc.z), fabsf(a.w * sc.w))));
    }

    // warp reduce
    #pragma unroll
    for (int o = 16; o; o >>= 1)
        m = fmaxf(m, __shfl_xor_sync(0xFFFFFFFFu, m, o));
    __shared__ float sm[32];
    const int lane = threadIdx.x & 31, wid = threadIdx.x >> 5;
    if (lane == 0) sm[wid] = m;
    __syncthreads();
    const int nwarps = blockDim.x >> 5;
    if (wid == 0) {
        m = (lane < nwarps) ? sm[lane] : 0.f;
        #pragma unroll
        for (int o = 16; o; o >>= 1)
            m = fmaxf(m, __shfl_xor_sync(0xFFFFFFFFu, m, o));
        if (lane == 0) atomicMax(&g_absmax[slot], __float_as_uint(m));
    }
}

// One block per token, one float4 per thread (blockDim == dim4).
// ids are int32 (JAX without x64 downcasts int64 -> int32).
__global__ void gather_kernel(const int* __restrict__ ids,
                              const float4* __restrict__ tw0,
                              const float4* __restrict__ tw1,
                              const float4* __restrict__ tw2,
                              const float4* __restrict__ tw3,
                              const float4* __restrict__ ts0,
                              const float4* __restrict__ ts1,
                              const float4* __restrict__ ts2,
                              const float4* __restrict__ ts3,
                              float4* __restrict__ out,
                              int dim4, long b0, long b1, long b2, long vocab) {
    const int tok = blockIdx.x;
    long id = (long)__ldg(&ids[tok]);
    if (id < 0) id = 0;
    if (id >= vocab) id = vocab - 1;

    const float4* w; const float4* s;
    float mv = 0.f; int slot = 0;
    if (id < b0)      { w = tw0 + (size_t)id * dim4;        s = ts0; }
    else if (id < b1) { w = tw1 + (size_t)(id - b0) * dim4; s = ts1; mv = 127.f; slot = 1; }
    else if (id < b2) { w = tw2 + (size_t)(id - b1) * dim4; s = ts2; mv = 31.f;  slot = 2; }
    else              { w = tw3 + (size_t)(id - b2) * dim4; s = ts3; mv = 7.f;   slot = 3; }

    const int c = threadIdx.x;
    // Issue both independent loads before the dependent math.
    float4 v  = w[c];
    float4 sc = s[c];

    float scale = 1.f;
    if (slot > 0) scale = fmaxf(__uint_as_float(g_absmax[slot]), 1e-8f) / mv;

    v.x *= sc.x; v.y *= sc.y; v.z *= sc.z; v.w *= sc.w;
    if (slot > 0) {
        v.x = fminf(fmaxf(rintf(v.x / scale), -mv), mv) * scale;
        v.y = fminf(fmaxf(rintf(v.y / scale), -mv), mv) * scale;
        v.z = fminf(fmaxf(rintf(v.z / scale), -mv), mv) * scale;
        v.w = fminf(fmaxf(rintf(v.w / scale), -mv), mv) * scale;
    }
    out[(size_t)tok * dim4 + c] = v;
}

extern "C" void kernel_launch(void* const* d_in, const int* in_sizes, int n_in,
                              void* d_out, int out_size) {
    const int*   ids = (const int*)d_in[0];
    const float* tw0 = (const float*)d_in[1];
    const float* tw1 = (const float*)d_in[2];
    const float* tw2 = (const float*)d_in[3];
    const float* tw3 = (const float*)d_in[4];
    const float* ts0 = (const float*)d_in[5];
    const float* ts1 = (const float*)d_in[6];
    const float* ts2 = (const float*)d_in[7];
    const float* ts3 = (const float*)d_in[8];

    const int dim  = in_sizes[5];          // ts0 element count = embedding dim
    const int dim4 = dim / 4;
    const int ntok = in_sizes[0];

    const int r0 = in_sizes[1] / dim;      // tier row counts
    const int r1 = in_sizes[2] / dim;
    const int r2 = in_sizes[3] / dim;
    const int r3 = in_sizes[4] / dim;
    const long b0 = r0;                    // cumulative id boundaries
    const long b1 = b0 + r1;
    const long b2 = b1 + r2;
    const long vocab = b2 + r3;

    // ~16 rows per block per tier
    const int nb1 = (r1 + 15) / 16;
    const int nb2 = (r2 + 15) / 16;
    const int nb3 = (r3 + 15) / 16;

    // Zero the absmax slots with a memset node (cheaper than a kernel launch).
    void* absmax_addr = nullptr;
    cudaGetSymbolAddress(&absmax_addr, g_absmax);
    cudaMemsetAsync(absmax_addr, 0, 4 * sizeof(unsigned int));

    absmax3_kernel<<<nb1 + nb2 + nb3, dim4>>>(
        (const float4*)tw1, (const float4*)tw2, (const float4*)tw3,
        (const float4*)ts1, (const float4*)ts2, (const float4*)ts3,
        r1, r2, r3, nb1, nb2, nb3, dim4);

    gather_kernel<<<ntok, dim4>>>(
        ids,
        (const float4*)tw0, (const float4*)tw1, (const float4*)tw2, (const float4*)tw3,
        (const float4*)ts0, (const float4*)ts1, (const float4*)ts2, (const float4*)ts3,
        (float4*)d_out, dim4, b0, b1, b2, vocab);
}